// round 16
// baseline (speedup 1.0000x reference)
#include <cuda_runtime.h>
#include <cuda_fp16.h>
#include <math.h>
#include <stdint.h>

#define N_NODES 25000
#define N_EDGES 400000
#define EMBED   128
#define NHEADS  8
#define DKH     16

// ---------------- scratch (static device globals; no allocation) -----------
__device__ __align__(16) __half g_Qh[N_NODES * EMBED];   // fp16 Q (gather-only)
__device__ __align__(16) __half g_Kh[N_NODES * EMBED];   // fp16 K (gather-only)
__device__ __align__(16) __half g_Vh[N_NODES * EMBED];   // fp16 V (gather-only)
__device__ __align__(16) float g_agg[N_NODES * EMBED];   // normalized sum(e*v)/z
__device__ int   g_cnt[N_NODES];                         // edges per dst
__device__ int   g_start[N_NODES];                       // exclusive prefix
__device__ int   g_cur[N_NODES];                         // scatter cursor
__device__ __align__(8) int2 g_sedge[N_EDGES];           // (eid, src) sorted by dst

// ---------------- K0: init (counters only) --------------------------------
__global__ void init_kernel() {
    int i = blockIdx.x * blockDim.x + threadIdx.x;
    if (i < N_NODES) g_cnt[i] = 0;
}

// ---------------- sort by dst: hist -> scan -> scatter ---------------------
__global__ void hist_kernel(const int* __restrict__ ei) {
    int e = blockIdx.x * blockDim.x + threadIdx.x;
    if (e < N_EDGES) atomicAdd(&g_cnt[ei[e]], 1);
}

__global__ void scan_kernel() {   // single block, 1024 threads
    __shared__ int s[1024];
    int t = threadIdx.x;
    const int CH = (N_NODES + 1023) / 1024;   // 25
    int b0 = t * CH;
    int sum = 0;
    for (int i = 0; i < CH; ++i) {
        int idx = b0 + i;
        if (idx < N_NODES) sum += g_cnt[idx];
    }
    s[t] = sum;
    __syncthreads();
    for (int off = 1; off < 1024; off <<= 1) {
        int v = (t >= off) ? s[t - off] : 0;
        __syncthreads();
        s[t] += v;
        __syncthreads();
    }
    int excl = (t == 0) ? 0 : s[t - 1];
    for (int i = 0; i < CH; ++i) {
        int idx = b0 + i;
        if (idx < N_NODES) {
            g_start[idx] = excl;
            g_cur[idx]   = excl;
            excl += g_cnt[idx];
        }
    }
}

__global__ void scatter_kernel(const int* __restrict__ ei) {
    int e = blockIdx.x * blockDim.x + threadIdx.x;
    if (e < N_EDGES) {
        int dst = ei[e];
        int src = ei[N_EDGES + e];
        int pos = atomicAdd(&g_cur[dst], 1);
        g_sedge[pos] = make_int2(e, src);
    }
}

// ================= tf32 tensor-core GEMM: Out = X @ W^T + b ================
// cp.async double-buffered staging: 2-stage smem ring, prefetch chunk k+1
// while computing chunk k. tf32 cvt happens at fragment load (same rna
// rounding as before). OOB rows zero-fill via cp.async src-size 0.
#define GM_BLK 128
#define GKC    32
#define STAGE_F (GM_BLK * GKC)            // floats per buffer per operand
#define GEMM_SMEM_BYTES (4 * STAGE_F * 4) // xs[2] + ws[2]

__device__ __forceinline__ float to_tf32(float x) {
    float r;
    asm("cvt.rna.tf32.f32 %0, %1;" : "=f"(r) : "f"(x));
    return r;
}

__device__ __forceinline__ unsigned su(float v) {
    return __float_as_uint(to_tf32(v));
}

__device__ __forceinline__ void mma_tf32(float c[4], const unsigned a[4], const unsigned b[2]) {
    asm volatile(
        "mma.sync.aligned.m16n8k8.row.col.f32.tf32.tf32.f32 "
        "{%0,%1,%2,%3}, {%4,%5,%6,%7}, {%8,%9}, {%0,%1,%2,%3};\n"
        : "+f"(c[0]), "+f"(c[1]), "+f"(c[2]), "+f"(c[3])
        : "r"(a[0]), "r"(a[1]), "r"(a[2]), "r"(a[3]), "r"(b[0]), "r"(b[1]));
}

__device__ __forceinline__ void cp_async16(unsigned dst_smem, const void* src, int sz) {
    asm volatile("cp.async.cg.shared.global [%0], [%1], 16, %2;"
                 :: "r"(dst_smem), "l"(src), "r"(sz));
}
__device__ __forceinline__ void cp_commit() {
    asm volatile("cp.async.commit_group;" ::: "memory");
}
template <int N>
__device__ __forceinline__ void cp_wait() {
    asm volatile("cp.async.wait_group %0;" :: "n"(N) : "memory");
}

// stage one K-chunk of X and W into the given buffers (async)
__device__ __forceinline__
void stage_chunk(const float* __restrict__ X, const float* __restrict__ W,
                 int nrows, int n0, int kc, unsigned xs_smem, unsigned ws_smem,
                 int tid) {
#pragma unroll
    for (int r = 0; r < 4; ++r) {
        int idx = r * 256 + tid;
        int n  = idx >> 3;
        int k4 = idx & 7;
        int ks = (4 * k4) ^ ((n & 7) << 2);
        const float* src = X + (size_t)(n0 + n) * EMBED + kc + 4 * k4;
        int sz = (n0 + n < nrows) ? 16 : 0;
        cp_async16(xs_smem + (unsigned)(n * GKC + ks) * 4, src, sz);
    }
#pragma unroll
    for (int r = 0; r < 4; ++r) {
        int idx = r * 256 + tid;
        int j  = idx >> 3;
        int k4 = idx & 7;
        int ks = (4 * k4) ^ ((j & 7) << 2);
        const float* src = W + (size_t)j * EMBED + kc + 4 * k4;
        cp_async16(ws_smem + (unsigned)(j * GKC + ks) * 4, src, 16);
    }
}

// out_half: if nonzero, Out is a __half* buffer (fp16 store for gather inputs)
__device__ __forceinline__
void gemm_body(const float* __restrict__ X, const float* __restrict__ W,
               const float* __restrict__ bias, void* __restrict__ Out,
               int nrows, int n0, int out_half) {
    extern __shared__ float smemblk[];
    float* xs_buf[2] = { smemblk,               smemblk + STAGE_F };
    float* ws_buf[2] = { smemblk + 2 * STAGE_F, smemblk + 3 * STAGE_F };
    unsigned xs_sm[2], ws_sm[2];
#pragma unroll
    for (int s = 0; s < 2; ++s) {
        xs_sm[s] = (unsigned)__cvta_generic_to_shared(xs_buf[s]);
        ws_sm[s] = (unsigned)__cvta_generic_to_shared(ws_buf[s]);
    }

    int tid  = threadIdx.x;
    int lane = tid & 31;
    int w    = tid >> 5;

    int mq = w & 3;    // rows 32*mq .. +31
    int nh = w >> 2;   // cols 64*nh .. +63

    float c[2][8][4];
#pragma unroll
    for (int mi = 0; mi < 2; ++mi)
#pragma unroll
        for (int ni = 0; ni < 8; ++ni)
#pragma unroll
            for (int q = 0; q < 4; ++q) c[mi][ni][q] = 0.0f;

    const int NCHUNK = EMBED / GKC;   // 4

    // prefetch chunk 0
    stage_chunk(X, W, nrows, n0, 0, xs_sm[0], ws_sm[0], tid);
    cp_commit();

    for (int ci = 0; ci < NCHUNK; ++ci) {
        int cur = ci & 1;
        if (ci + 1 < NCHUNK) {
            // buffer (ci+1)&1 was last read in iteration ci-1; the trailing
            // __syncthreads of that iteration protects this overwrite
            stage_chunk(X, W, nrows, n0, (ci + 1) * GKC,
                        xs_sm[cur ^ 1], ws_sm[cur ^ 1], tid);
            cp_commit();
            cp_wait<1>();
        } else {
            cp_wait<0>();
        }
        __syncthreads();

        const float* xs = xs_buf[cur];
        const float* ws = ws_buf[cur];
#pragma unroll
        for (int k0 = 0; k0 < GKC; k0 += 8) {
            unsigned a[2][4];
#pragma unroll
            for (int mi = 0; mi < 2; ++mi) {
                int rrow = mq * 32 + mi * 16 + (lane >> 2);
                int sw = (rrow & 7) << 2;
                int kA = k0 + (lane & 3);
                a[mi][0] = su(xs[rrow * GKC + (kA ^ sw)]);
                a[mi][1] = su(xs[(rrow + 8) * GKC + (kA ^ sw)]);
                a[mi][2] = su(xs[rrow * GKC + ((kA + 4) ^ sw)]);
                a[mi][3] = su(xs[(rrow + 8) * GKC + ((kA + 4) ^ sw)]);
            }
            unsigned b[8][2];
#pragma unroll
            for (int ni = 0; ni < 8; ++ni) {
                int j = nh * 64 + ni * 8 + (lane >> 2);
                int sw = (j & 7) << 2;
                int kB = k0 + (lane & 3);
                b[ni][0] = su(ws[j * GKC + (kB ^ sw)]);
                b[ni][1] = su(ws[j * GKC + ((kB + 4) ^ sw)]);
            }
#pragma unroll
            for (int mi = 0; mi < 2; ++mi)
#pragma unroll
                for (int ni = 0; ni < 8; ++ni)
                    mma_tf32(c[mi][ni], a[mi], b[ni]);
        }
        __syncthreads();
    }

#pragma unroll
    for (int mi = 0; mi < 2; ++mi) {
        int r = n0 + mq * 32 + mi * 16 + (lane >> 2);
#pragma unroll
        for (int ni = 0; ni < 8; ++ni) {
            int col = nh * 64 + ni * 8 + 2 * (lane & 3);
            float b0 = bias[col], b1 = bias[col + 1];
            if (out_half) {
                __half* Oh = (__half*)Out;
                if (r < nrows)
                    *(__half2*)(Oh + (size_t)r * EMBED + col) =
                        __floats2half2_rn(c[mi][ni][0] + b0, c[mi][ni][1] + b1);
                if (r + 8 < nrows)
                    *(__half2*)(Oh + (size_t)(r + 8) * EMBED + col) =
                        __floats2half2_rn(c[mi][ni][2] + b0, c[mi][ni][3] + b1);
            } else {
                float* Of = (float*)Out;
                if (r < nrows)
                    *(float2*)(Of + (size_t)r * EMBED + col) =
                        make_float2(c[mi][ni][0] + b0, c[mi][ni][1] + b1);
                if (r + 8 < nrows)
                    *(float2*)(Of + (size_t)(r + 8) * EMBED + col) =
                        make_float2(c[mi][ni][2] + b0, c[mi][ni][3] + b1);
            }
        }
    }
}

// fused Q/K/V (fp16 out): blockIdx.y selects projection
__global__ __launch_bounds__(256)
void qkv3_kernel(const float* __restrict__ X,
                 const float* __restrict__ Wq, const float* __restrict__ bq,
                 const float* __restrict__ Wk, const float* __restrict__ bk,
                 const float* __restrict__ Wv, const float* __restrict__ bv) {
    const float* W; const float* b; __half* O;
    if (blockIdx.y == 0)      { W = Wq; b = bq; O = g_Qh; }
    else if (blockIdx.y == 1) { W = Wk; b = bk; O = g_Kh; }
    else                      { W = Wv; b = bv; O = g_Vh; }
    gemm_body(X, W, b, O, N_NODES, blockIdx.x * GM_BLK, 1);
}

__global__ __launch_bounds__(256)
void gemm_tf32_kernel(const float* __restrict__ X,
                      const float* __restrict__ W,
                      const float* __restrict__ bias,
                      float* __restrict__ Out,
                      int nrows) {
    gemm_body(X, W, bias, Out, nrows, blockIdx.x * GM_BLK, 0);
}

// ---------------- gather: shfl-free (edge, head) lane mapping --------------
// One warp per dst node, 4 edges per iteration. lane = el*8 + hl with
// el = lane>>3 (edge slot), hl = lane&7 (head). fp16 head slice = 16 halves
// = 32B = two uint4 loads; the 16-term dot is fully lane-local: ZERO shuffles
// in the loop, 1 exp per lane. Indices fetched per-lane and software-
// pipelined one iteration ahead. Cross-edge-group reduction once in the
// epilogue (xor 8,16). Softmax shift-invariant (logits O(8), no max
// subtraction); fp32 accumulation; stores NORMALIZED fp32 agg.
__global__ __launch_bounds__(256)
void gather_kernel(const float* __restrict__ bias,
                   float* __restrict__ out_logits) {
    int warp = (blockIdx.x * blockDim.x + threadIdx.x) >> 5;
    if (warp >= N_NODES) return;
    int lane = threadIdx.x & 31;
    int el   = lane >> 3;          // edge slot within iteration group
    int hl   = lane & 7;           // head owned by this lane
    int n = warp;

    // Q slice for head hl -> 16 floats in registers (two uint4 = 16 halves)
    float qf[16];
    {
        uint4 qr0 = *(const uint4*)(g_Qh + (size_t)n * EMBED + hl * DKH);
        uint4 qr1 = *(const uint4*)(g_Qh + (size_t)n * EMBED + hl * DKH + 8);
        const unsigned* qu0 = (const unsigned*)&qr0;
        const unsigned* qu1 = (const unsigned*)&qr1;
#pragma unroll
        for (int j = 0; j < 4; ++j) {
            float2 fa = __half22float2(*reinterpret_cast<const __half2*>(&qu0[j]));
            qf[2 * j + 0] = fa.x; qf[2 * j + 1] = fa.y;
            float2 fb = __half22float2(*reinterpret_cast<const __half2*>(&qu1[j]));
            qf[8 + 2 * j + 0] = fb.x; qf[8 + 2 * j + 1] = fb.y;
        }
    }

    float acc[16];
#pragma unroll
    for (int j = 0; j < 16; ++j) acc[j] = 0.0f;
    float accz = 0.0f;

    int cnt  = g_cnt[n];
    int base = g_start[n];

    // pipelined index fetch: each lane loads ITS edge's (eid, src) directly
    int2 se = g_sedge[base + min(el, cnt - 1)];

    for (int i = 0; i < cnt; i += 4) {
        int2 cur = se;
        int nxt = i + 4 + el;
        if (nxt < cnt) se = g_sedge[base + nxt];

        bool valid = (i + el) < cnt;
        size_t rowoff = (size_t)cur.y * EMBED + hl * DKH;

        uint4 kr0 = *(const uint4*)(g_Kh + rowoff);
        uint4 kr1 = *(const uint4*)(g_Kh + rowoff + 8);
        uint4 vr0 = *(const uint4*)(g_Vh + rowoff);
        uint4 vr1 = *(const uint4*)(g_Vh + rowoff + 8);
        float bv = bias[cur.x * NHEADS + hl];

        const unsigned* ku0 = (const unsigned*)&kr0;
        const unsigned* ku1 = (const unsigned*)&kr1;
        float dot = 0.0f;
#pragma unroll
        for (int j = 0; j < 4; ++j) {
            float2 fa = __half22float2(*reinterpret_cast<const __half2*>(&ku0[j]));
            dot += qf[2 * j] * fa.x + qf[2 * j + 1] * fa.y;
        }
#pragma unroll
        for (int j = 0; j < 4; ++j) {
            float2 fa = __half22float2(*reinterpret_cast<const __half2*>(&ku1[j]));
            dot += qf[8 + 2 * j] * fa.x + qf[8 + 2 * j + 1] * fa.y;
        }

        float logit = 0.25f * dot + bv;     // scale = 1/sqrt(16)
        if (valid) out_logits[cur.x * NHEADS + hl] = logit;

        float ev = valid ? __expf(logit) : 0.0f;
        accz += ev;

        const unsigned* vu0 = (const unsigned*)&vr0;
        const unsigned* vu1 = (const unsigned*)&vr1;
#pragma unroll
        for (int j = 0; j < 4; ++j) {
            float2 fa = __half22float2(*reinterpret_cast<const __half2*>(&vu0[j]));
            acc[2 * j]     += ev * fa.x;
            acc[2 * j + 1] += ev * fa.y;
        }
#pragma unroll
        for (int j = 0; j < 4; ++j) {
            float2 fa = __half22float2(*reinterpret_cast<const __half2*>(&vu1[j]));
            acc[8 + 2 * j]     += ev * fa.x;
            acc[8 + 2 * j + 1] += ev * fa.y;
        }
    }

    // one-time cross-edge-group reduction (lanes differing in bits 3,4)
    accz += __shfl_xor_sync(0xffffffffu, accz, 8);
    accz += __shfl_xor_sync(0xffffffffu, accz, 16);
#pragma unroll
    for (int j = 0; j < 16; ++j) {
        acc[j] += __shfl_xor_sync(0xffffffffu, acc[j], 8);
        acc[j] += __shfl_xor_sync(0xffffffffu, acc[j], 16);
    }

    float inv = (accz > 0.0f) ? (1.0f / accz) : 0.0f;
    // lane writes its el-quarter of head hl's slice
    float4 wv = make_float4(acc[el * 4 + 0] * inv, acc[el * 4 + 1] * inv,
                            acc[el * 4 + 2] * inv, acc[el * 4 + 3] * inv);
    *(float4*)(g_agg + (size_t)n * EMBED + hl * DKH + el * 4) = wv;
}

// ---------------- launch --------------------------------------------------
// Prep chain (init/hist/scan/scatter) is independent of qkv3; run it on a
// side stream forked/joined with events so it overlaps the QKV GEMM inside
// the captured graph. Streams/events/attrs set up lazily on the FIRST call
// (the uncaptured correctness run) and reused on every captured call.
extern "C" void kernel_launch(void* const* d_in, const int* in_sizes, int n_in,
                              void* d_out, int out_size) {
    const float* x    = (const float*)d_in[0];
    const int*   ei   = (const int*)d_in[1];
    const float* bias = (const float*)d_in[2];
    const float* Wq   = (const float*)d_in[3];
    const float* bq   = (const float*)d_in[4];
    const float* Wk   = (const float*)d_in[5];
    const float* bk   = (const float*)d_in[6];
    const float* Wv   = (const float*)d_in[7];
    const float* bv   = (const float*)d_in[8];
    const float* Wo   = (const float*)d_in[9];
    const float* bo   = (const float*)d_in[10];

    float* out        = (float*)d_out;                       // [N_NODES, 128]
    float* out_logits = (float*)d_out + N_NODES * EMBED;     // [E, H, 1]

    static cudaStream_t s2 = nullptr;
    static cudaEvent_t ev_fork = nullptr, ev_join = nullptr;
    if (s2 == nullptr) {
        cudaStreamCreateWithFlags(&s2, cudaStreamNonBlocking);
        cudaEventCreateWithFlags(&ev_fork, cudaEventDisableTiming);
        cudaEventCreateWithFlags(&ev_join, cudaEventDisableTiming);
        cudaFuncSetAttribute(qkv3_kernel,
            cudaFuncAttributeMaxDynamicSharedMemorySize, GEMM_SMEM_BYTES);
        cudaFuncSetAttribute(gemm_tf32_kernel,
            cudaFuncAttributeMaxDynamicSharedMemorySize, GEMM_SMEM_BYTES);
    }

    // fork: s2 ordered after anything already on the main (default) stream
    cudaEventRecord(ev_fork, 0);
    cudaStreamWaitEvent(s2, ev_fork, 0);

    // prep chain on side stream
    init_kernel<<<(N_NODES + 255) / 256, 256, 0, s2>>>();
    hist_kernel<<<(N_EDGES + 255) / 256, 256, 0, s2>>>(ei);
    scan_kernel<<<1, 1024, 0, s2>>>();
    scatter_kernel<<<(N_EDGES + 255) / 256, 256, 0, s2>>>(ei);
    cudaEventRecord(ev_join, s2);

    // QKV GEMM on main stream, concurrent with prep
    int gblk = (N_NODES + GM_BLK - 1) / GM_BLK;
    dim3 qkvgrid(gblk, 3);
    qkv3_kernel<<<qkvgrid, 256, GEMM_SMEM_BYTES>>>(x, Wq, bq, Wk, bk, Wv, bv);

    // join: gather needs both qkv3 (main) and prep (s2)
    cudaStreamWaitEvent(0, ev_join, 0);

    int nwarp_blocks = (N_NODES * 32 + 255) / 256;
    gather_kernel<<<nwarp_blocks, 256>>>(bias, out_logits);

    float* gA; cudaGetSymbolAddress((void**)&gA, g_agg);
    gemm_tf32_kernel<<<gblk, 256, GEMM_SMEM_BYTES>>>(gA, Wo, bo, out, N_NODES);
}